// round 13
// baseline (speedup 1.0000x reference)
#include <cuda_runtime.h>
#include <cuda_bf16.h>

#define BB 1024
#define T_HIST 50
#define ENC_IN 96
#define ENC_H 128
#define G4 (4*ENC_H)          // 512
#define CDE_H 64
#define CHN 33
#define NZ 10000
#define MLP_H 128
#define W2_ROWS (CHN*CDE_H)   // 2112
#define N_STEPS 16
#define NCTA_CDE 264

// ----------------------------------------------------------------------------
// Scratch (static device globals — no allocation)
// ----------------------------------------------------------------------------
__device__ float g_xW[BB*T_HIST*G4];
__device__ float g_seq0[BB*T_HIST*ENC_H];
__device__ float g_h1[2][BB*ENC_H];
__device__ float g_z[BB*CDE_H];
__device__ float g_k[6][BB*CDE_H];
__device__ float g_f[BB*W2_ROWS];

// tf32 fragment-ordered operands for the W2 GEMM
__device__ unsigned g_aF[262144];
__device__ unsigned g_w2F[540672];

// sync state
__device__ unsigned g_grpCnt[64];   // LSTM per-group counters
__device__ unsigned g_pBar;         // persistent-CDE barrier counter

__global__ void zero_cnt() {
    if (threadIdx.x < 64) g_grpCnt[threadIdx.x] = 0u;
    if (threadIdx.x == 0) g_pBar = 0u;
}

// ----------------------------------------------------------------------------
// tf32 helpers (portable PTX — ptxas here targets plain sm_103, no tcgen05)
// ----------------------------------------------------------------------------
__device__ __forceinline__ unsigned f2tf32(float v) {
    unsigned r;
    asm("cvt.rna.tf32.f32 %0, %1;" : "=r"(r) : "f"(v));
    return r;
}
__device__ __forceinline__ void mma_tf32(float c[4], uint4 a, uint2 b) {
    asm volatile(
        "mma.sync.aligned.m16n8k8.row.col.f32.tf32.tf32.f32 "
        "{%0,%1,%2,%3}, {%4,%5,%6,%7}, {%8,%9}, {%0,%1,%2,%3};"
        : "+f"(c[0]), "+f"(c[1]), "+f"(c[2]), "+f"(c[3])
        : "r"(a.x), "r"(a.y), "r"(a.z), "r"(a.w), "r"(b.x), "r"(b.y));
}

// ----------------------------------------------------------------------------
// One-time W2 -> tf32 hi/lo fragment-order conversion (per launch).
// ----------------------------------------------------------------------------
__global__ void __launch_bounds__(256)
w2_frag(const float* __restrict__ W2)
{
    int e = blockIdx.x * 256 + threadIdx.x;
    if (e >= W2_ROWS * 128) return;
    int n = e >> 7, k = e & 127;
    float v = W2[e];
    unsigned hb = f2tf32(v);
    unsigned lb = f2tf32(v - __uint_as_float(hb));
    int ks = k >> 3, k8 = k & 7, nt = n >> 3;
    int lane = (n & 7) * 4 + (k8 & 3);
    int slot = k8 >> 2;
    int idx = ((ks * 264 + nt) * 2) * 64 + lane * 2 + slot;
    g_w2F[idx] = hb;
    g_w2F[idx + 64] = lb;
}

// ----------------------------------------------------------------------------
// Persistent CDE kernel: 264 CTAs, 96 iterations, grid barriers via monotonic
// L2 counter. Phase A = W2 tile GEMM (all CTAs). Phase B = contract + prep
// (CTAs 0..255, 4 batch rows each — same rows every iter, so z/k stay
// SM-coherent; cross-SM data read via __ldcg).
// ----------------------------------------------------------------------------
__device__ __forceinline__ void cde_bar(unsigned &bars) {
    __syncthreads();
    bars++;
    if (threadIdx.x == 0) {
        __threadfence();
        atomicAdd(&g_pBar, 1u);
        unsigned tgt = bars * (unsigned)NCTA_CDE;
        while (__ldcg(&g_pBar) < tgt) __nanosleep(30);
    }
    __syncthreads();
}

__device__ void cde_phaseA(unsigned* pool, int bx, int by, const float* __restrict__ b2)
{
    unsigned* As = pool;
    unsigned* Bs = pool + 8192;
    const int tid = threadIdx.x;
    const int w = tid >> 5, l = tid & 31;
    const int wm = w & 3, wn = w >> 2;
    const int m0 = bx * 128, n0 = by * 64;

    float acc[2][4][4];
#pragma unroll
    for (int mt = 0; mt < 2; mt++)
#pragma unroll
        for (int nt = 0; nt < 4; nt++)
#pragma unroll
            for (int i = 0; i < 4; i++) acc[mt][nt][i] = 0.f;

    const uint4* srcA = (const uint4*)g_aF;
    const uint4* srcB = (const uint4*)g_w2F;

    for (int c = 0; c < 4; c++) {
        if (c) __syncthreads();
#pragma unroll
        for (int q = 0; q < 8; q++) {
            int e4 = tid + q * 256;
            int blk = e4 >> 5, w32 = e4 & 31;
            int ksl = blk >> 4, rest = blk & 15;
            int gblk = (((c * 4 + ksl) * 64) + bx * 8 + (rest >> 1)) * 2 + (rest & 1);
            ((uint4*)As)[e4] = __ldcg(&srcA[gblk * 32 + w32]);   // cross-SM producer
        }
#pragma unroll
        for (int q = 0; q < 4; q++) {
            int e4 = tid + q * 256;
            int blk = e4 >> 4, w16 = e4 & 15;
            int ksl = blk >> 4, rest = blk & 15;
            int gblk = ((c * 4 + ksl) * 264 + by * 8 + (rest >> 1)) * 2 + (rest & 1);
            ((uint4*)Bs)[e4] = srcB[gblk * 16 + w16];            // constant
        }
        __syncthreads();

#pragma unroll
        for (int kstep = 0; kstep < 4; kstep++) {
            uint4 Ahi[2], Alo[2];
            uint2 Bhi[4], Blo[4];
#pragma unroll
            for (int mt = 0; mt < 2; mt++) {
                int mtile = wm * 2 + mt;
                int base = ((kstep * 8 + mtile) * 2) * 128 + l * 4;
                Ahi[mt] = *(const uint4*)&As[base];
                Alo[mt] = *(const uint4*)&As[base + 128];
            }
#pragma unroll
            for (int nt = 0; nt < 4; nt++) {
                int ntile = wn * 4 + nt;
                int base = ((kstep * 8 + ntile) * 2) * 64 + l * 2;
                Bhi[nt] = *(const uint2*)&Bs[base];
                Blo[nt] = *(const uint2*)&Bs[base + 64];
            }
#pragma unroll
            for (int mt = 0; mt < 2; mt++)
#pragma unroll
                for (int nt = 0; nt < 4; nt++) {
                    mma_tf32(acc[mt][nt], Ahi[mt], Bhi[nt]);
                    mma_tf32(acc[mt][nt], Ahi[mt], Blo[nt]);
                    mma_tf32(acc[mt][nt], Alo[mt], Bhi[nt]);
                }
        }
    }

    __syncthreads();
    float* S = (float*)pool;
    const int g = l >> 2, tq = l & 3;
#pragma unroll
    for (int mt = 0; mt < 2; mt++)
#pragma unroll
        for (int nt = 0; nt < 4; nt++) {
            int row = wm * 32 + mt * 16 + g;
            int col = wn * 32 + nt * 8 + tq * 2;
            S[row * 68 + col]           = acc[mt][nt][0];
            S[row * 68 + col + 1]       = acc[mt][nt][1];
            S[(row + 8) * 68 + col]     = acc[mt][nt][2];
            S[(row + 8) * 68 + col + 1] = acc[mt][nt][3];
        }
    __syncthreads();
#pragma unroll
    for (int q = 0; q < 8; q++) {
        int e = tid + q * 256;
        int r = e >> 4, c4 = (e & 15) * 4;
        float4 v = *(const float4*)&S[r * 68 + c4];
        float4 o;
        o.x = tanhf(v.x + b2[n0 + c4 + 0]);
        o.y = tanhf(v.y + b2[n0 + c4 + 1]);
        o.z = tanhf(v.z + b2[n0 + c4 + 2]);
        o.w = tanhf(v.w + b2[n0 + c4 + 3]);
        *(float4*)&g_f[(size_t)(m0 + r) * W2_ROWS + n0 + c4] = o;
    }
}

__device__ void cde_phaseB(unsigned* pool, int r0,
                           const float* __restrict__ coeffs,
                           const float* __restrict__ gamma,
                           const float* __restrict__ beta,
                           const float* __restrict__ W1,
                           const float* __restrict__ b1,
                           int do_contract, int sidx, int idx, float u, int is_last,
                           const float* bu, int do_prep, const float* arc, int nk)
{
    float* W1s = (float*)pool;                  // [64][128] = 8192 floats
    float* zs  = (float*)pool + 8192;           // [4][65]
    float* dXs = (float*)pool + 8452;           // [4][33]
    float* znT = (float*)pool + 8584;           // [64][4], 16B-aligned
    const int tid = threadIdx.x;

    if (do_prep) {
#pragma unroll
        for (int q = 0; q < 32; q++) {
            int e = tid + q * 256;
            W1s[(e & 63) * 128 + (e >> 6)] = W1[e];
        }
    }

    const int r = tid >> 6, h = tid & 63;       // one (row, h) per thread
    if (do_contract) {
        for (int e = tid; e < 4 * CHN; e += 256) {
            int rr = e / CHN, ch = e - rr * CHN;
            size_t base = ((size_t)(r0 + rr) * 4 + idx) * (4 * CHN);
            float A1 = coeffs[base + CHN + ch];
            float A2 = coeffs[base + 2 * CHN + ch];
            float A3 = coeffs[base + 3 * CHN + ch];
            dXs[rr * CHN + ch] = A1 + 2.f * A2 * u + 3.f * A3 * u * u;
        }
        __syncthreads();
        const float* fr = g_f + (size_t)(r0 + r) * W2_ROWS + h * CHN;
        float acc = 0.f;
#pragma unroll
        for (int ch = 0; ch < CHN; ch++) acc += __ldcg(&fr[ch]) * dXs[r * CHN + ch];
        size_t gi = (size_t)(r0 + r) * CDE_H + h;
        if (is_last) {
            float z = g_z[gi] + bu[0] * g_k[0][gi] + bu[1] * g_k[2][gi]
                    + bu[2] * g_k[3][gi] + bu[3] * g_k[4][gi] + bu[4] * acc;
            g_z[gi] = z;
            zs[r * 65 + h] = z;
        } else {
            g_k[sidx][gi] = acc;
            float v = g_z[gi];
            for (int j = 0; j < nk; j++)
                v += arc[j] * ((j == sidx) ? acc : g_k[j][gi]);
            zs[r * 65 + h] = v;
        }
    } else {
        zs[r * 65 + h] = g_z[(size_t)(r0 + r) * CDE_H + h];
    }
    if (!do_prep) return;
    __syncthreads();

    if (tid < 128) {
        int w = tid >> 5, lane = tid & 31;
        float x0 = zs[w * 65 + lane], x1 = zs[w * 65 + lane + 32];
        float s = x0 + x1;
#pragma unroll
        for (int d = 1; d < 32; d <<= 1) s += __shfl_xor_sync(0xffffffffu, s, d);
        float m = s * (1.f / 64.f);
        float d0 = x0 - m, d1 = x1 - m;
        float q2 = d0 * d0 + d1 * d1;
#pragma unroll
        for (int d = 1; d < 32; d <<= 1) q2 += __shfl_xor_sync(0xffffffffu, q2, d);
        float rs = rsqrtf(q2 * (1.f / 64.f) + 1e-5f);
        znT[lane * 4 + w]        = d0 * rs * gamma[lane] + beta[lane];
        znT[(lane + 32) * 4 + w] = d1 * rs * gamma[lane + 32] + beta[lane + 32];
    }
    __syncthreads();

    if (tid < 128) {
        float acc4[4] = {0.f, 0.f, 0.f, 0.f};
#pragma unroll 8
        for (int k = 0; k < 64; k++) {
            float4 z4 = *(const float4*)&znT[k * 4];
            float wv = W1s[k * 128 + tid];
            acc4[0] += z4.x * wv; acc4[1] += z4.y * wv;
            acc4[2] += z4.z * wv; acc4[3] += z4.w * wv;
        }
        float bb = b1[tid];
        int ks = tid >> 3, k8 = tid & 7;
#pragma unroll
        for (int i = 0; i < 4; i++) {
            int rr = r0 + i;
            float v = fmaxf(acc4[i] + bb, 0.f);
            unsigned hb = f2tf32(v);
            unsigned lb = f2tf32(v - __uint_as_float(hb));
            int mt = rr >> 4, r16 = rr & 15;
            int lane = (r16 & 7) * 4 + (k8 & 3);
            int slot = ((r16 >> 3) & 1) | ((k8 >> 2) << 1);
            int idxF = ((ks * 64 + mt) * 2) * 128 + lane * 4 + slot;
            g_aF[idxF] = hb;
            g_aF[idxF + 128] = lb;
        }
    }
}

__global__ void __launch_bounds__(256, 2)
cde_persist(const float* __restrict__ coeffs,
            const float* __restrict__ gamma, const float* __restrict__ beta,
            const float* __restrict__ W1, const float* __restrict__ b1,
            const float* __restrict__ b2)
{
    extern __shared__ unsigned pool[];          // 48KB
    const int id = blockIdx.x;
    unsigned bars = 0;

    const double DT = 1.0 / 16.0;
    const double COFFd[6] = {0.0, 1.0/5, 3.0/10, 4.0/5, 8.0/9, 1.0};
    const float BUc[5] = {
        (float)(DT*35.0/384), (float)(DT*500.0/1113), (float)(DT*125.0/192),
        (float)(DT*-2187.0/6784), (float)(DT*11.0/84) };
    const float ACFc[6][5] = {
        {0.f, 0.f, 0.f, 0.f, 0.f},
        {(float)(DT*1.0/5), 0.f, 0.f, 0.f, 0.f},
        {(float)(DT*3.0/40), (float)(DT*9.0/40), 0.f, 0.f, 0.f},
        {(float)(DT*44.0/45), (float)(DT*-56.0/15), (float)(DT*32.0/9), 0.f, 0.f},
        {(float)(DT*19372.0/6561), (float)(DT*-25360.0/2187),
         (float)(DT*64448.0/6561), (float)(DT*-212.0/729), 0.f},
        {(float)(DT*9017.0/3168), (float)(DT*-355.0/33),
         (float)(DT*46732.0/5247), (float)(DT*49.0/176), (float)(DT*-5103.0/18656)} };

    // prologue: initial prep (no contract)
    if (id < 256)
        cde_phaseB(pool, id * 4, coeffs, gamma, beta, W1, b1,
                   0, 0, 0, 0.f, 0, BUc, 1, ACFc[0], 0);
    cde_bar(bars);

    for (int it = 0; it < 96; it++) {
        int i = it / 6, s = it - i * 6;

        cde_phaseA(pool, id & 7, id >> 3, b2);
        cde_bar(bars);

        float ts = (float)((i + COFFd[s]) * DT);
        int idx = (int)floorf(ts / 0.25f);
        if (idx < 0) idx = 0;
        if (idx > 3) idx = 3;
        float u = ts - (float)idx * 0.25f;

        int last = (s == 5);
        int do_prep = (it < 95);
        int nk = last ? 0 : (s + 1);
        const float* arc = last ? ACFc[0] : ACFc[s + 1];

        if (id < 256)
            cde_phaseB(pool, id * 4, coeffs, gamma, beta, W1, b1,
                       1, s, idx, u, last, BUc, do_prep, arc, nk);
        if (it < 95) cde_bar(bars);
    }
}

// ----------------------------------------------------------------------------
// Generalized 3xTF32 GEMM: C = A @ B^T (+bias). (round-12 verified)
// ----------------------------------------------------------------------------
__global__ void __launch_bounds__(256)
gemm_tf32(const float* __restrict__ A, const float* __restrict__ Bm,
          const float* __restrict__ bias, float* __restrict__ C,
          int M, int N, int K)
{
    extern __shared__ unsigned pool[];
    unsigned* As = pool;
    unsigned* Bs = pool + 8192;
    const int tid = threadIdx.x;
    const int w = tid >> 5, l = tid & 31;
    const int wm = w & 3, wn = w >> 2;
    const int m0 = blockIdx.x * 128, n0 = blockIdx.y * 64;
    const int KC = K >> 5;

    float acc[2][4][4];
#pragma unroll
    for (int mt = 0; mt < 2; mt++)
#pragma unroll
        for (int nt = 0; nt < 4; nt++)
#pragma unroll
            for (int i = 0; i < 4; i++) acc[mt][nt][i] = 0.f;

    for (int c = 0; c < KC; c++) {
        const int k0 = c * 32;
        if (c) __syncthreads();
#pragma unroll
        for (int q = 0; q < 16; q++) {
            int e = tid + q * 256;
            int r = e >> 5, kk = e & 31;
            float v = A[(size_t)(m0 + r) * K + k0 + kk];
            unsigned hb = f2tf32(v);
            unsigned lb = f2tf32(v - __uint_as_float(hb));
            int kstep = kk >> 3, k8 = kk & 7;
            int mtile = r >> 4, r16 = r & 15;
            int lane = (r16 & 7) * 4 + (k8 & 3);
            int slot = ((r16 >> 3) & 1) | ((k8 >> 2) << 1);
            int base = ((kstep * 8 + mtile) * 2) * 128 + lane * 4 + slot;
            As[base] = hb;
            As[base + 128] = lb;
        }
#pragma unroll
        for (int q = 0; q < 8; q++) {
            int e = tid + q * 256;
            int n = e >> 5, kk = e & 31;
            float v = Bm[(size_t)(n0 + n) * K + k0 + kk];
            unsigned hb = f2tf32(v);
            unsigned lb = f2tf32(v - __uint_as_float(hb));
            int kstep = kk >> 3, k8 = kk & 7;
            int ntile = n >> 3;
            int lane = (n & 7) * 4 + (k8 & 3);
            int slot = (k8 >> 2) & 1;
            int base = ((kstep * 8 + ntile) * 2) * 64 + lane * 2 + slot;
            Bs[base] = hb;
            Bs[base + 64] = lb;
        }
        __syncthreads();

#pragma unroll
        for (int kstep = 0; kstep < 4; kstep++) {
            uint4 Ahi[2], Alo[2];
            uint2 Bhi[4], Blo[4];
#pragma unroll
            for (int mt = 0; mt < 2; mt++) {
                int mtile = wm * 2 + mt;
                int base = ((kstep * 8 + mtile) * 2) * 128 + l * 4;
                Ahi[mt] = *(const uint4*)&As[base];
                Alo[mt] = *(const uint4*)&As[base + 128];
            }
#pragma unroll
            for (int nt = 0; nt < 4; nt++) {
                int ntile = wn * 4 + nt;
                int base = ((kstep * 8 + ntile) * 2) * 64 + l * 2;
                Bhi[nt] = *(const uint2*)&Bs[base];
                Blo[nt] = *(const uint2*)&Bs[base + 64];
            }
#pragma unroll
            for (int mt = 0; mt < 2; mt++)
#pragma unroll
                for (int nt = 0; nt < 4; nt++) {
                    mma_tf32(acc[mt][nt], Ahi[mt], Bhi[nt]);
                    mma_tf32(acc[mt][nt], Ahi[mt], Blo[nt]);
                    mma_tf32(acc[mt][nt], Alo[mt], Bhi[nt]);
                }
        }
    }

    __syncthreads();
    float* S = (float*)pool;
    const int g = l >> 2, tq = l & 3;
#pragma unroll
    for (int mt = 0; mt < 2; mt++)
#pragma unroll
        for (int nt = 0; nt < 4; nt++) {
            int row = wm * 32 + mt * 16 + g;
            int col = wn * 32 + nt * 8 + tq * 2;
            S[row * 68 + col]           = acc[mt][nt][0];
            S[row * 68 + col + 1]       = acc[mt][nt][1];
            S[(row + 8) * 68 + col]     = acc[mt][nt][2];
            S[(row + 8) * 68 + col + 1] = acc[mt][nt][3];
        }
    __syncthreads();
#pragma unroll
    for (int q = 0; q < 8; q++) {
        int e = tid + q * 256;
        int r = e >> 4, c4 = (e & 15) * 4;
        float4 v = *(const float4*)&S[r * 68 + c4];
        if (bias) {
            v.x += bias[n0 + c4 + 0];
            v.y += bias[n0 + c4 + 1];
            v.z += bias[n0 + c4 + 2];
            v.w += bias[n0 + c4 + 3];
        }
        *(float4*)&C[(size_t)(m0 + r) * N + n0 + c4] = v;
    }
}

// ----------------------------------------------------------------------------
// Generic C = act(A @ B^T + bias). Scalar FFMA (z0 map + final projection).
// ----------------------------------------------------------------------------
template<int ACT>
__global__ void __launch_bounds__(256)
gemm_tn(const float* __restrict__ A, const float* __restrict__ Bm,
        const float* __restrict__ bias, float* __restrict__ C,
        int M, int N, int K)
{
    __shared__ __align__(16) float As[16][64];
    __shared__ __align__(16) float Bs[16][64];
    const int m0 = blockIdx.x * 64;
    const int n0 = blockIdx.y * 64;
    const int tid = threadIdx.x;
    const int tr = tid >> 4;
    const int tc = tid & 15;

    float acc[4][4];
#pragma unroll
    for (int i = 0; i < 4; i++)
#pragma unroll
        for (int j = 0; j < 4; j++) acc[i][j] = 0.f;

    const int ml = tid >> 2;
    const int kq = (tid & 3) * 4;

    for (int k0 = 0; k0 < K; k0 += 16) {
        {
            float4 v = *(const float4*)(A + (size_t)(m0 + ml) * K + k0 + kq);
            As[kq+0][ml] = v.x; As[kq+1][ml] = v.y; As[kq+2][ml] = v.z; As[kq+3][ml] = v.w;
            float4 w = make_float4(0.f, 0.f, 0.f, 0.f);
            if (n0 + ml < N)
                w = *(const float4*)(Bm + (size_t)(n0 + ml) * K + k0 + kq);
            Bs[kq+0][ml] = w.x; Bs[kq+1][ml] = w.y; Bs[kq+2][ml] = w.z; Bs[kq+3][ml] = w.w;
        }
        __syncthreads();
#pragma unroll
        for (int kk = 0; kk < 16; kk++) {
            float4 a4 = *(const float4*)&As[kk][tr*4];
            float4 b4 = *(const float4*)&Bs[kk][tc*4];
            float av[4] = {a4.x, a4.y, a4.z, a4.w};
            float bv[4] = {b4.x, b4.y, b4.z, b4.w};
#pragma unroll
            for (int i = 0; i < 4; i++)
#pragma unroll
                for (int j = 0; j < 4; j++) acc[i][j] += av[i] * bv[j];
        }
        __syncthreads();
    }

#pragma unroll
    for (int j = 0; j < 4; j++) {
        int n = n0 + tc*4 + j;
        if (n >= N) continue;
        float bb = bias ? bias[n] : 0.f;
#pragma unroll
        for (int i = 0; i < 4; i++) {
            float v = acc[i][j] + bb;
            if (ACT == 1) v = tanhf(v);
            else if (ACT == 2) v = fmaxf(v, 0.f);
            C[(size_t)(m0 + tr*4 + i) * N + n] = v;
        }
    }
}

// ----------------------------------------------------------------------------
// Persistent LSTM layer — round-11 version (465us/layer), unchanged.
// ----------------------------------------------------------------------------
__global__ void __launch_bounds__(512)
lstm_persist(const float* __restrict__ xw,
             const float* __restrict__ Whh,
             const float* __restrict__ bih, const float* __restrict__ bhh,
             float* __restrict__ h_buf, int h_sb, int mode, int nsteps, int cbase)
{
    extern __shared__ __align__(16) float Wsm[];
    __shared__ __align__(16) float As[ENC_H][33];
    __shared__ float Gs[32][132];
    __shared__ float bsum[128];

    const int grp = blockIdx.x & 31;
    const int b0 = grp * 32;
    const int h0 = (blockIdx.x >> 5) * 32;
    const int tid = threadIdx.x;
    const int tr = tid >> 5;
    const int tc = tid & 31;

#pragma unroll
    for (int q = 0; q < 8; q++) {
        int e = tid + q * 512;
        int c = e & 127, kq = (e >> 7) * 4;
        int jg = (c >> 5) * ENC_H + h0 + (c & 31);
        float4 v = *(const float4*)(Whh + (size_t)jg * ENC_H + kq);
        Wsm[(kq+0)*128 + c] = v.x; Wsm[(kq+1)*128 + c] = v.y;
        Wsm[(kq+2)*128 + c] = v.z; Wsm[(kq+3)*128 + c] = v.w;
    }
    if (tid < 128) {
        int jg = (tid >> 5) * ENC_H + h0 + (tid & 31);
        bsum[tid] = bih[jg] + bhh[jg];
    }
    float creg[2] = {0.f, 0.f};
    __syncthreads();

    for (int t = 0; t < nsteps; t++) {
        float xr[2][4];
#pragma unroll
        for (int j = 0; j < 4; j++) {
            int c = tc*4 + j;
            int jg = (c >> 5) * ENC_H + h0 + (c & 31);
#pragma unroll
            for (int p = 0; p < 2; p++)
                xr[p][j] = xw[(size_t)(b0 + 2*tr + p) * (T_HIST*G4)
                              + (size_t)t * G4 + jg];
        }

        float acc[2][4];
#pragma unroll
        for (int p = 0; p < 2; p++)
#pragma unroll
            for (int j = 0; j < 4; j++) acc[p][j] = 0.f;

        if (t > 0) {
            if (tid == 0) {
                while (__ldcg(&g_grpCnt[cbase + grp]) < 4u * (unsigned)t)
                    __nanosleep(20);
            }
            __syncthreads();
            const float* hp = h_buf + (mode ? (size_t)((t-1) & 1) * BB * ENC_H
                                            : (size_t)(t-1) * ENC_H);
#pragma unroll
            for (int q = 0; q < 2; q++) {
                int e = tid + q * 512;
                int m = e & 31, kq = (e >> 5) * 4;
                float4 v = __ldcg((const float4*)(hp + (size_t)(b0 + m) * h_sb + kq));
                As[kq+0][m] = v.x; As[kq+1][m] = v.y; As[kq+2][m] = v.z; As[kq+3][m] = v.w;
            }
            __syncthreads();
#pragma unroll 8
            for (int kk = 0; kk < ENC_H; kk++) {
                float a0 = As[kk][2*tr];
                float a1 = As[kk][2*tr + 1];
                float4 w = *(const float4*)&Wsm[kk*128 + tc*4];
                acc[0][0] += a0 * w.x; acc[0][1] += a0 * w.y;
                acc[0][2] += a0 * w.z; acc[0][3] += a0 * w.w;
                acc[1][0] += a1 * w.x; acc[1][1] += a1 * w.y;
                acc[1][2] += a1 * w.z; acc[1][3] += a1 * w.w;
            }
        }

#pragma unroll
        for (int j = 0; j < 4; j++) {
            int c = tc*4 + j;
            float bb = bsum[c];
#pragma unroll
            for (int p = 0; p < 2; p++) {
                int r = 2*tr + p;
                Gs[r][c] = acc[p][j] + xr[p][j] + bb;
            }
        }
        __syncthreads();

        float* ho = h_buf + (mode ? (size_t)(t & 1) * BB * ENC_H : (size_t)t * ENC_H);
#pragma unroll
        for (int q = 0; q < 2; q++) {
            int e = tid + q * 512;
            int r = e >> 5, hh = e & 31;
            float gi = Gs[r][hh];
            float gf = Gs[r][32 + hh];
            float gg = Gs[r][64 + hh];
            float go = Gs[r][96 + hh];
            float si = 1.f / (1.f + expf(-gi));
            float sf = 1.f / (1.f + expf(-gf));
            float so = 1.f / (1.f + expf(-go));
            float tg = tanhf(gg);
            float cn = sf * creg[q] + si * tg;
            creg[q] = cn;
            float hn = so * tanhf(cn);
            ho[(size_t)(b0 + r) * h_sb + h0 + hh] = hn;
        }
        __syncthreads();
        if (tid == 0) {
            __threadfence();
            atomicAdd(&g_grpCnt[cbase + grp], 1u);
        }
    }
}

// ----------------------------------------------------------------------------
// Host orchestration
// ----------------------------------------------------------------------------
extern "C" void kernel_launch(void* const* d_in, const int* in_sizes, int n_in,
                              void* d_out, int out_size)
{
    const float* hist   = (const float*)d_in[0];
    const float* coeffs = (const float*)d_in[1];
    const float* W_ih0 = (const float*)d_in[3];
    const float* W_hh0 = (const float*)d_in[4];
    const float* b_ih0 = (const float*)d_in[5];
    const float* b_hh0 = (const float*)d_in[6];
    const float* W_ih1 = (const float*)d_in[7];
    const float* W_hh1 = (const float*)d_in[8];
    const float* b_ih1 = (const float*)d_in[9];
    const float* b_hh1 = (const float*)d_in[10];
    const float* W_map = (const float*)d_in[11];
    const float* b_map = (const float*)d_in[12];
    const float* gamma = (const float*)d_in[13];
    const float* beta  = (const float*)d_in[14];
    const float* W1    = (const float*)d_in[15];
    const float* b1    = (const float*)d_in[16];
    const float* W2    = (const float*)d_in[17];
    const float* b2    = (const float*)d_in[18];
    const float* W_pred = (const float*)d_in[19];
    const float* b_pred = (const float*)d_in[20];
    float* out = (float*)d_out;

    float *p_xW, *p_seq0, *p_h1, *p_z;
    cudaGetSymbolAddress((void**)&p_xW,   g_xW);
    cudaGetSymbolAddress((void**)&p_seq0, g_seq0);
    cudaGetSymbolAddress((void**)&p_h1,   g_h1);
    cudaGetSymbolAddress((void**)&p_z,    g_z);

    const int WSM_BYTES = 128 * 128 * 4;
    const int TC_SMEM = 12288 * 4;
    cudaFuncSetAttribute(lstm_persist, cudaFuncAttributeMaxDynamicSharedMemorySize, WSM_BYTES);
    cudaFuncSetAttribute(gemm_tf32, cudaFuncAttributeMaxDynamicSharedMemorySize, TC_SMEM);
    cudaFuncSetAttribute(cde_persist, cudaFuncAttributeMaxDynamicSharedMemorySize, TC_SMEM);

    zero_cnt<<<1, 64>>>();
    w2_frag<<<(W2_ROWS*128 + 255)/256, 256>>>(W2);

    // ---------------- LSTM layer 0 ----------------
    gemm_tf32<<<dim3(BB*T_HIST/128, G4/64), 256, TC_SMEM>>>(hist, W_ih0, nullptr, p_xW,
                                                            BB*T_HIST, G4, ENC_IN);
    lstm_persist<<<128, 512, WSM_BYTES>>>(p_xW, W_hh0, b_ih0, b_hh0,
                                          p_seq0, T_HIST*ENC_H, 0, T_HIST, 0);

    // ---------------- LSTM layer 1 ----------------
    gemm_tf32<<<dim3(BB*T_HIST/128, G4/64), 256, TC_SMEM>>>(p_seq0, W_ih1, nullptr, p_xW,
                                                            BB*T_HIST, G4, ENC_H);
    lstm_persist<<<128, 512, WSM_BYTES>>>(p_xW, W_hh1, b_ih1, b_hh1,
                                          p_h1, ENC_H, 1, T_HIST, 32);
    const float* context = p_h1 + (size_t)((T_HIST - 1) & 1) * BB * ENC_H;

    // ---------------- map to z0 ----------------
    gemm_tn<1><<<dim3(BB/64, 1), 256>>>(context, W_map, b_map, p_z, BB, CDE_H, ENC_H);

    // ---------------- Neural CDE: one persistent kernel ----------------
    cde_persist<<<NCTA_CDE, 256, TC_SMEM>>>(coeffs, gamma, beta, W1, b1, b2);

    // ---------------- final projection ----------------
    gemm_tn<0><<<dim3(BB/64, (NZ + 63)/64), 256>>>(p_z, W_pred, b_pred, out,
                                                   BB, NZ, CDE_H);
}

// round 14
// speedup vs baseline: 1.1170x; 1.1170x over previous
#include <cuda_runtime.h>
#include <cuda_bf16.h>

#define BB 1024
#define T_HIST 50
#define ENC_IN 96
#define ENC_H 128
#define G4 (4*ENC_H)          // 512
#define CDE_H 64
#define CHN 33
#define NZ 10000
#define MLP_H 128
#define W2_ROWS (CHN*CDE_H)   // 2112
#define N_STEPS 16

// ----------------------------------------------------------------------------
// Scratch (static device globals — no allocation)
// ----------------------------------------------------------------------------
__device__ float g_xW[BB*T_HIST*G4];
__device__ float g_seq0[BB*T_HIST*ENC_H];
__device__ float g_h1[2][BB*ENC_H];
__device__ float g_z[BB*CDE_H];
__device__ float g_k[6][BB*CDE_H];
__device__ float g_f[BB*W2_ROWS];

// tf32 fragment-ordered operands for the W2 GEMM
__device__ unsigned g_aF[262144];
__device__ unsigned g_w2F[540672];

// per-batch-group LSTM sync counters (32 per layer)
__device__ unsigned g_grpCnt[64];

__global__ void zero_cnt() {
    if (threadIdx.x < 64) g_grpCnt[threadIdx.x] = 0u;
}

// ----------------------------------------------------------------------------
// tf32 / cp.async helpers (portable PTX — ptxas here targets plain sm_103)
// ----------------------------------------------------------------------------
__device__ __forceinline__ unsigned f2tf32(float v) {
    unsigned r;
    asm("cvt.rna.tf32.f32 %0, %1;" : "=r"(r) : "f"(v));
    return r;
}
__device__ __forceinline__ void mma_tf32(float c[4], uint4 a, uint2 b) {
    asm volatile(
        "mma.sync.aligned.m16n8k8.row.col.f32.tf32.tf32.f32 "
        "{%0,%1,%2,%3}, {%4,%5,%6,%7}, {%8,%9}, {%0,%1,%2,%3};"
        : "+f"(c[0]), "+f"(c[1]), "+f"(c[2]), "+f"(c[3])
        : "r"(a.x), "r"(a.y), "r"(a.z), "r"(a.w), "r"(b.x), "r"(b.y));
}
__device__ __forceinline__ unsigned smem_u32(const void* p) {
    unsigned a;
    asm("{ .reg .u64 t; cvta.to.shared.u64 t, %1; cvt.u32.u64 %0, t; }"
        : "=r"(a) : "l"(p));
    return a;
}
__device__ __forceinline__ void cp_async16(unsigned dst, const void* src) {
    asm volatile("cp.async.cg.shared.global [%0], [%1], 16;"
                 :: "r"(dst), "l"(src));
}
__device__ __forceinline__ void cp_commit() {
    asm volatile("cp.async.commit_group;" ::: "memory");
}
template<int N>
__device__ __forceinline__ void cp_wait() {
    asm volatile("cp.async.wait_group %0;" :: "n"(N) : "memory");
}

// ----------------------------------------------------------------------------
// One-time W2 -> tf32 hi/lo fragment-order conversion (per launch).
// ----------------------------------------------------------------------------
__global__ void __launch_bounds__(256)
w2_frag(const float* __restrict__ W2)
{
    int e = blockIdx.x * 256 + threadIdx.x;
    if (e >= W2_ROWS * 128) return;
    int n = e >> 7, k = e & 127;
    float v = W2[e];
    unsigned hb = f2tf32(v);
    unsigned lb = f2tf32(v - __uint_as_float(hb));
    int ks = k >> 3, k8 = k & 7, nt = n >> 3;
    int lane = (n & 7) * 4 + (k8 & 3);
    int slot = k8 >> 2;
    int idx = ((ks * 264 + nt) * 2) * 64 + lane * 2 + slot;
    g_w2F[idx] = hb;
    g_w2F[idx + 64] = lb;
}

// ----------------------------------------------------------------------------
// W2 GEMM via 3xTF32 mma.sync, pre-fragmented operands, cp.async
// DOUBLE-BUFFERED staging (2 x 48KB stages = 96KB dynamic smem).
// CTA tile 128x64 (grid 8x33), 256 thr, 8 warps (4m x 2n), K chunked by 32.
// ----------------------------------------------------------------------------
__device__ __forceinline__ void w2_load_chunk(unsigned sbase, int c, int bx, int by,
                                              int tid)
{
    const uint4* srcA = (const uint4*)g_aF;
    const uint4* srcB = (const uint4*)g_w2F;
    unsigned sA = sbase;                 // 8192 u32 region
    unsigned sB = sbase + 8192 * 4;      // 4096 u32 region (byte offsets)
#pragma unroll
    for (int q = 0; q < 8; q++) {
        int e4 = tid + q * 256;
        int blk = e4 >> 5, w32 = e4 & 31;
        int ksl = blk >> 4, rest = blk & 15;
        int gblk = (((c * 4 + ksl) * 64) + bx * 8 + (rest >> 1)) * 2 + (rest & 1);
        cp_async16(sA + e4 * 16, &srcA[gblk * 32 + w32]);
    }
#pragma unroll
    for (int q = 0; q < 4; q++) {
        int e4 = tid + q * 256;
        int blk = e4 >> 4, w16 = e4 & 15;
        int ksl = blk >> 4, rest = blk & 15;
        int gblk = ((c * 4 + ksl) * 264 + by * 8 + (rest >> 1)) * 2 + (rest & 1);
        cp_async16(sB + e4 * 16, &srcB[gblk * 16 + w16]);
    }
    cp_commit();
}

__global__ void __launch_bounds__(256)
gemm_w2_tc(const float* __restrict__ b2, float* __restrict__ Fout)
{
    extern __shared__ __align__(16) unsigned pool[];   // 24576 u32 = 96KB
    const int tid = threadIdx.x;
    const int w = tid >> 5, l = tid & 31;
    const int wm = w & 3, wn = w >> 2;
    const int bx = blockIdx.x, by = blockIdx.y;
    const int m0 = bx * 128, n0 = by * 64;
    const unsigned sbase = smem_u32(pool);

    float acc[2][4][4];
#pragma unroll
    for (int mt = 0; mt < 2; mt++)
#pragma unroll
        for (int nt = 0; nt < 4; nt++)
#pragma unroll
            for (int i = 0; i < 4; i++) acc[mt][nt][i] = 0.f;

    w2_load_chunk(sbase, 0, bx, by, tid);

    for (int c = 0; c < 4; c++) {
        if (c < 3) {
            w2_load_chunk(sbase + ((c + 1) & 1) * 12288 * 4, c + 1, bx, by, tid);
            cp_wait<1>();
        } else {
            cp_wait<0>();
        }
        __syncthreads();

        unsigned* As = pool + (c & 1) * 12288;
        unsigned* Bs = As + 8192;
#pragma unroll
        for (int kstep = 0; kstep < 4; kstep++) {
            uint4 Ahi[2], Alo[2];
            uint2 Bhi[4], Blo[4];
#pragma unroll
            for (int mt = 0; mt < 2; mt++) {
                int mtile = wm * 2 + mt;
                int base = ((kstep * 8 + mtile) * 2) * 128 + l * 4;
                Ahi[mt] = *(const uint4*)&As[base];
                Alo[mt] = *(const uint4*)&As[base + 128];
            }
#pragma unroll
            for (int nt = 0; nt < 4; nt++) {
                int ntile = wn * 4 + nt;
                int base = ((kstep * 8 + ntile) * 2) * 64 + l * 2;
                Bhi[nt] = *(const uint2*)&Bs[base];
                Blo[nt] = *(const uint2*)&Bs[base + 64];
            }
#pragma unroll
            for (int mt = 0; mt < 2; mt++)
#pragma unroll
                for (int nt = 0; nt < 4; nt++) {
                    mma_tf32(acc[mt][nt], Ahi[mt], Bhi[nt]);
                    mma_tf32(acc[mt][nt], Ahi[mt], Blo[nt]);
                    mma_tf32(acc[mt][nt], Alo[mt], Bhi[nt]);
                }
        }
        __syncthreads();
    }

    // epilogue: fragments -> padded smem -> coalesced float4 stores
    float* S = (float*)pool;                    // 128 x 68 floats = 34.8KB
    const int g = l >> 2, tq = l & 3;
#pragma unroll
    for (int mt = 0; mt < 2; mt++)
#pragma unroll
        for (int nt = 0; nt < 4; nt++) {
            int row = wm * 32 + mt * 16 + g;
            int col = wn * 32 + nt * 8 + tq * 2;
            S[row * 68 + col]           = acc[mt][nt][0];
            S[row * 68 + col + 1]       = acc[mt][nt][1];
            S[(row + 8) * 68 + col]     = acc[mt][nt][2];
            S[(row + 8) * 68 + col + 1] = acc[mt][nt][3];
        }
    __syncthreads();
#pragma unroll
    for (int q = 0; q < 8; q++) {
        int e = tid + q * 256;
        int r = e >> 4, c4 = (e & 15) * 4;
        float4 v = *(const float4*)&S[r * 68 + c4];
        float4 o;
        o.x = tanhf(v.x + b2[n0 + c4 + 0]);
        o.y = tanhf(v.y + b2[n0 + c4 + 1]);
        o.z = tanhf(v.z + b2[n0 + c4 + 2]);
        o.w = tanhf(v.w + b2[n0 + c4 + 3]);
        *(float4*)&Fout[(size_t)(m0 + r) * W2_ROWS + n0 + c4] = o;
    }
}

// ----------------------------------------------------------------------------
// Generalized 3xTF32 GEMM: C = A @ B^T (+bias). (round-12 verified, unchanged)
// ----------------------------------------------------------------------------
__global__ void __launch_bounds__(256)
gemm_tf32(const float* __restrict__ A, const float* __restrict__ Bm,
          const float* __restrict__ bias, float* __restrict__ C,
          int M, int N, int K)
{
    extern __shared__ unsigned pool[];
    unsigned* As = pool;
    unsigned* Bs = pool + 8192;
    const int tid = threadIdx.x;
    const int w = tid >> 5, l = tid & 31;
    const int wm = w & 3, wn = w >> 2;
    const int m0 = blockIdx.x * 128, n0 = blockIdx.y * 64;
    const int KC = K >> 5;

    float acc[2][4][4];
#pragma unroll
    for (int mt = 0; mt < 2; mt++)
#pragma unroll
        for (int nt = 0; nt < 4; nt++)
#pragma unroll
            for (int i = 0; i < 4; i++) acc[mt][nt][i] = 0.f;

    for (int c = 0; c < KC; c++) {
        const int k0 = c * 32;
        if (c) __syncthreads();
#pragma unroll
        for (int q = 0; q < 16; q++) {
            int e = tid + q * 256;
            int r = e >> 5, kk = e & 31;
            float v = A[(size_t)(m0 + r) * K + k0 + kk];
            unsigned hb = f2tf32(v);
            unsigned lb = f2tf32(v - __uint_as_float(hb));
            int kstep = kk >> 3, k8 = kk & 7;
            int mtile = r >> 4, r16 = r & 15;
            int lane = (r16 & 7) * 4 + (k8 & 3);
            int slot = ((r16 >> 3) & 1) | ((k8 >> 2) << 1);
            int base = ((kstep * 8 + mtile) * 2) * 128 + lane * 4 + slot;
            As[base] = hb;
            As[base + 128] = lb;
        }
#pragma unroll
        for (int q = 0; q < 8; q++) {
            int e = tid + q * 256;
            int n = e >> 5, kk = e & 31;
            float v = Bm[(size_t)(n0 + n) * K + k0 + kk];
            unsigned hb = f2tf32(v);
            unsigned lb = f2tf32(v - __uint_as_float(hb));
            int kstep = kk >> 3, k8 = kk & 7;
            int ntile = n >> 3;
            int lane = (n & 7) * 4 + (k8 & 3);
            int slot = (k8 >> 2) & 1;
            int base = ((kstep * 8 + ntile) * 2) * 64 + lane * 2 + slot;
            Bs[base] = hb;
            Bs[base + 64] = lb;
        }
        __syncthreads();

#pragma unroll
        for (int kstep = 0; kstep < 4; kstep++) {
            uint4 Ahi[2], Alo[2];
            uint2 Bhi[4], Blo[4];
#pragma unroll
            for (int mt = 0; mt < 2; mt++) {
                int mtile = wm * 2 + mt;
                int base = ((kstep * 8 + mtile) * 2) * 128 + l * 4;
                Ahi[mt] = *(const uint4*)&As[base];
                Alo[mt] = *(const uint4*)&As[base + 128];
            }
#pragma unroll
            for (int nt = 0; nt < 4; nt++) {
                int ntile = wn * 4 + nt;
                int base = ((kstep * 8 + ntile) * 2) * 64 + l * 2;
                Bhi[nt] = *(const uint2*)&Bs[base];
                Blo[nt] = *(const uint2*)&Bs[base + 64];
            }
#pragma unroll
            for (int mt = 0; mt < 2; mt++)
#pragma unroll
                for (int nt = 0; nt < 4; nt++) {
                    mma_tf32(acc[mt][nt], Ahi[mt], Bhi[nt]);
                    mma_tf32(acc[mt][nt], Ahi[mt], Blo[nt]);
                    mma_tf32(acc[mt][nt], Alo[mt], Bhi[nt]);
                }
        }
    }

    __syncthreads();
    float* S = (float*)pool;
    const int g = l >> 2, tq = l & 3;
#pragma unroll
    for (int mt = 0; mt < 2; mt++)
#pragma unroll
        for (int nt = 0; nt < 4; nt++) {
            int row = wm * 32 + mt * 16 + g;
            int col = wn * 32 + nt * 8 + tq * 2;
            S[row * 68 + col]           = acc[mt][nt][0];
            S[row * 68 + col + 1]       = acc[mt][nt][1];
            S[(row + 8) * 68 + col]     = acc[mt][nt][2];
            S[(row + 8) * 68 + col + 1] = acc[mt][nt][3];
        }
    __syncthreads();
#pragma unroll
    for (int q = 0; q < 8; q++) {
        int e = tid + q * 256;
        int r = e >> 4, c4 = (e & 15) * 4;
        float4 v = *(const float4*)&S[r * 68 + c4];
        if (bias) {
            v.x += bias[n0 + c4 + 0];
            v.y += bias[n0 + c4 + 1];
            v.z += bias[n0 + c4 + 2];
            v.w += bias[n0 + c4 + 3];
        }
        *(float4*)&C[(size_t)(m0 + r) * N + n0 + c4] = v;
    }
}

// ----------------------------------------------------------------------------
// Generic C = act(A @ B^T + bias). Scalar FFMA (z0 map + final projection).
// ----------------------------------------------------------------------------
template<int ACT>
__global__ void __launch_bounds__(256)
gemm_tn(const float* __restrict__ A, const float* __restrict__ Bm,
        const float* __restrict__ bias, float* __restrict__ C,
        int M, int N, int K)
{
    __shared__ __align__(16) float As[16][64];
    __shared__ __align__(16) float Bs[16][64];
    const int m0 = blockIdx.x * 64;
    const int n0 = blockIdx.y * 64;
    const int tid = threadIdx.x;
    const int tr = tid >> 4;
    const int tc = tid & 15;

    float acc[4][4];
#pragma unroll
    for (int i = 0; i < 4; i++)
#pragma unroll
        for (int j = 0; j < 4; j++) acc[i][j] = 0.f;

    const int ml = tid >> 2;
    const int kq = (tid & 3) * 4;

    for (int k0 = 0; k0 < K; k0 += 16) {
        {
            float4 v = *(const float4*)(A + (size_t)(m0 + ml) * K + k0 + kq);
            As[kq+0][ml] = v.x; As[kq+1][ml] = v.y; As[kq+2][ml] = v.z; As[kq+3][ml] = v.w;
            float4 w = make_float4(0.f, 0.f, 0.f, 0.f);
            if (n0 + ml < N)
                w = *(const float4*)(Bm + (size_t)(n0 + ml) * K + k0 + kq);
            Bs[kq+0][ml] = w.x; Bs[kq+1][ml] = w.y; Bs[kq+2][ml] = w.z; Bs[kq+3][ml] = w.w;
        }
        __syncthreads();
#pragma unroll
        for (int kk = 0; kk < 16; kk++) {
            float4 a4 = *(const float4*)&As[kk][tr*4];
            float4 b4 = *(const float4*)&Bs[kk][tc*4];
            float av[4] = {a4.x, a4.y, a4.z, a4.w};
            float bv[4] = {b4.x, b4.y, b4.z, b4.w};
#pragma unroll
            for (int i = 0; i < 4; i++)
#pragma unroll
                for (int j = 0; j < 4; j++) acc[i][j] += av[i] * bv[j];
        }
        __syncthreads();
    }

#pragma unroll
    for (int j = 0; j < 4; j++) {
        int n = n0 + tc*4 + j;
        if (n >= N) continue;
        float bb = bias ? bias[n] : 0.f;
#pragma unroll
        for (int i = 0; i < 4; i++) {
            float v = acc[i][j] + bb;
            if (ACT == 1) v = tanhf(v);
            else if (ACT == 2) v = fmaxf(v, 0.f);
            C[(size_t)(m0 + tr*4 + i) * N + n] = v;
        }
    }
}

// ----------------------------------------------------------------------------
// Persistent LSTM layer, 256 threads, 4x4 microtile (smem-crossbar fix):
// per k-step each thread does 2x LDS.128 for 16 FMA (was 3 LDS for 8 FMA).
// 128 CTAs = 32 batch-groups x 4 h-tiles; per-group sync counters.
// ----------------------------------------------------------------------------
__global__ void __launch_bounds__(256)
lstm_persist(const float* __restrict__ xw,
             const float* __restrict__ Whh,
             const float* __restrict__ bih, const float* __restrict__ bhh,
             float* __restrict__ h_buf, int h_sb, int mode, int nsteps, int cbase)
{
    extern __shared__ __align__(16) float Wsm[];   // [128 k][128 c] = 64KB
    __shared__ __align__(16) float As[ENC_H][36];  // [k][m], 16B-aligned rows
    __shared__ __align__(16) float Gs[32][132];    // stride 528B (16B-aligned)
    __shared__ float bsum[128];

    const int grp = blockIdx.x & 31;
    const int b0 = grp * 32;
    const int h0 = (blockIdx.x >> 5) * 32;
    const int tid = threadIdx.x;
    const int tr = tid >> 5;        // 0..7  -> rows tr*4..tr*4+3
    const int tc = tid & 31;        // cols tc*4..tc*4+3 of 128 gate-cols

    // one-time weight load: Wsm[k*128 + c] = Whh[jg(c)][k]
#pragma unroll
    for (int q = 0; q < 16; q++) {
        int e = tid + q * 256;            // 0..4095 float4 units
        int c = e & 127, kq = (e >> 7) * 4;
        int jg = (c >> 5) * ENC_H + h0 + (c & 31);
        float4 v = *(const float4*)(Whh + (size_t)jg * ENC_H + kq);
        Wsm[(kq+0)*128 + c] = v.x; Wsm[(kq+1)*128 + c] = v.y;
        Wsm[(kq+2)*128 + c] = v.z; Wsm[(kq+3)*128 + c] = v.w;
    }
    if (tid < 128) {
        int jg = (tid >> 5) * ENC_H + h0 + (tid & 31);
        bsum[tid] = bih[tid >= 0 ? jg : 0] + bhh[jg];
    }
    float creg[4] = {0.f, 0.f, 0.f, 0.f};
    __syncthreads();

    // column block for this thread: cols tc*4..+3 map to one gate block
    const int cb = tc * 4;
    const int jg0 = (cb >> 5) * ENC_H + h0 + (cb & 31);   // 4 consecutive jg

    for (int t = 0; t < nsteps; t++) {
        // prefetch this step's xw slice (4 rows x 4 cols, float4 per row)
        float4 xr[4];
#pragma unroll
        for (int i = 0; i < 4; i++) {
            xr[i] = *(const float4*)(xw + (size_t)(b0 + tr*4 + i) * (T_HIST*G4)
                                     + (size_t)t * G4 + jg0);
        }

        float acc[4][4];
#pragma unroll
        for (int i = 0; i < 4; i++)
#pragma unroll
            for (int j = 0; j < 4; j++) acc[i][j] = 0.f;

        if (t > 0) {
            if (tid == 0) {
                while (__ldcg(&g_grpCnt[cbase + grp]) < 4u * (unsigned)t)
                    __nanosleep(20);
            }
            __syncthreads();
            const float* hp = h_buf + (mode ? (size_t)((t-1) & 1) * BB * ENC_H
                                            : (size_t)(t-1) * ENC_H);
#pragma unroll
            for (int q = 0; q < 4; q++) {
                int e = tid + q * 256;        // 0..1023 float4 units
                int m = e & 31, kq = (e >> 5) * 4;
                float4 v = __ldcg((const float4*)(hp + (size_t)(b0 + m) * h_sb + kq));
                As[kq+0][m] = v.x; As[kq+1][m] = v.y; As[kq+2][m] = v.z; As[kq+3][m] = v.w;
            }
            __syncthreads();
#pragma unroll 8
            for (int kk = 0; kk < ENC_H; kk++) {
                float4 a4 = *(const float4*)&As[kk][tr*4];
                float4 w4 = *(const float4*)&Wsm[kk*128 + cb];
                float av[4] = {a4.x, a4.y, a4.z, a4.w};
                float wv[4] = {w4.x, w4.y, w4.z, w4.w};
#pragma unroll
                for (int i = 0; i < 4; i++)
#pragma unroll
                    for (int j = 0; j < 4; j++) acc[i][j] += av[i] * wv[j];
            }
        }

        // gate pre-activations -> Gs (float4 stores)
#pragma unroll
        for (int i = 0; i < 4; i++) {
            float4 g;
            g.x = acc[i][0] + xr[i].x + bsum[cb + 0];
            g.y = acc[i][1] + xr[i].y + bsum[cb + 1];
            g.z = acc[i][2] + xr[i].z + bsum[cb + 2];
            g.w = acc[i][3] + xr[i].w + bsum[cb + 3];
            *(float4*)&Gs[tr*4 + i][cb] = g;
        }
        __syncthreads();

        // gates + c/h update (c in registers: fixed (r,hh) per thread)
        float* ho = h_buf + (mode ? (size_t)(t & 1) * BB * ENC_H : (size_t)t * ENC_H);
#pragma unroll
        for (int q = 0; q < 4; q++) {
            int e = tid + q * 256;
            int r = e >> 5, hh = e & 31;
            float gi = Gs[r][hh];
            float gf = Gs[r][32 + hh];
            float gg = Gs[r][64 + hh];
            float go = Gs[r][96 + hh];
            float si = 1.f / (1.f + expf(-gi));
            float sf = 1.f / (1.f + expf(-gf));
            float so = 1.f / (1.f + expf(-go));
            float tg = tanhf(gg);
            float cn = sf * creg[q] + si * tg;
            creg[q] = cn;
            float hn = so * tanhf(cn);
            ho[(size_t)(b0 + r) * h_sb + h0 + hh] = hn;
        }
        __syncthreads();
        if (tid == 0) {
            __threadfence();
            atomicAdd(&g_grpCnt[cbase + grp], 1u);
        }
    }
}

// ----------------------------------------------------------------------------
// Fused CDE kernel: contract(stage sidx) + prep(next stage). (round-12, 
// verified) grid = 256 CTAs (4 batch rows each), 128 threads.
// ----------------------------------------------------------------------------
__global__ void __launch_bounds__(128)
cde_cp(const float* __restrict__ coeffs,
       const float* __restrict__ gamma, const float* __restrict__ beta,
       const float* __restrict__ W1, const float* __restrict__ b1,
       int do_contract, int sidx, int idx, float u, int is_last,
       float c1, float c3, float c4, float c5, float c6,
       int do_prep, float a0, float a1, float a2, float a3, float a4, int nk)
{
    __shared__ float W1s[64 * 128];              // 32KB, [k][j]
    __shared__ float zs[4][65];
    __shared__ float dXs[4][CHN];
    __shared__ __align__(16) float znT[64][4];
    const int r0 = blockIdx.x * 4;
    const int tid = threadIdx.x;

    if (do_prep) {
#pragma unroll
        for (int q = 0; q < 64; q++) {
            int e = tid + q * 128;
            int j = e >> 6, k = e & 63;
            W1s[k * 128 + j] = W1[e];
        }
    }

    if (do_contract) {
        for (int e = tid; e < 4 * CHN; e += 128) {
            int r = e / CHN, ch = e - r * CHN;
            size_t base = ((size_t)(r0 + r) * 4 + idx) * (4 * CHN);
            float A1 = coeffs[base + CHN + ch];
            float A2 = coeffs[base + 2 * CHN + ch];
            float A3 = coeffs[base + 3 * CHN + ch];
            dXs[r][ch] = A1 + 2.f * A2 * u + 3.f * A3 * u * u;
        }
        __syncthreads();
        const float av[5] = {a0, a1, a2, a3, a4};
#pragma unroll
        for (int q = 0; q < 2; q++) {
            int e = tid + q * 128;
            int r = e >> 6, h = e & 63;
            const float* fr = g_f + (size_t)(r0 + r) * W2_ROWS + h * CHN;
            float acc = 0.f;
#pragma unroll
            for (int ch = 0; ch < CHN; ch++) acc += fr[ch] * dXs[r][ch];
            size_t gi = (size_t)(r0 + r) * CDE_H + h;
            if (is_last) {
                float z = g_z[gi] + c1 * g_k[0][gi] + c3 * g_k[2][gi]
                        + c4 * g_k[3][gi] + c5 * g_k[4][gi] + c6 * acc;
                g_z[gi] = z;
                zs[r][h] = z;
            } else {
                g_k[sidx][gi] = acc;
                float v = g_z[gi];
                for (int j = 0; j < nk; j++)
                    v += av[j] * ((j == sidx) ? acc : g_k[j][gi]);
                zs[r][h] = v;
            }
        }
    } else {
#pragma unroll
        for (int q = 0; q < 2; q++) {
            int e = tid + q * 128;
            int r = e >> 6, h = e & 63;
            zs[r][h] = g_z[(size_t)(r0 + r) * CDE_H + h];
        }
    }
    if (!do_prep) return;
    __syncthreads();

    // LayerNorm: warp w handles row w (32 lanes x 2 cols)
    {
        int w = tid >> 5, lane = tid & 31;
        float x0 = zs[w][lane], x1 = zs[w][lane + 32];
        float s = x0 + x1;
#pragma unroll
        for (int d = 1; d < 32; d <<= 1) s += __shfl_xor_sync(0xffffffffu, s, d);
        float m = s * (1.f / 64.f);
        float d0 = x0 - m, d1 = x1 - m;
        float q2 = d0 * d0 + d1 * d1;
#pragma unroll
        for (int d = 1; d < 32; d <<= 1) q2 += __shfl_xor_sync(0xffffffffu, q2, d);
        float rs = rsqrtf(q2 * (1.f / 64.f) + 1e-5f);
        znT[lane][w]      = d0 * rs * gamma[lane] + beta[lane];
        znT[lane + 32][w] = d1 * rs * gamma[lane + 32] + beta[lane + 32];
    }
    __syncthreads();

    // GEMM: thread tid owns MLP col tid for 4 rows
    float acc4[4] = {0.f, 0.f, 0.f, 0.f};
#pragma unroll 8
    for (int k = 0; k < 64; k++) {
        float4 z4 = *(const float4*)&znT[k][0];
        float wv = W1s[k * 128 + tid];
        acc4[0] += z4.x * wv; acc4[1] += z4.y * wv;
        acc4[2] += z4.z * wv; acc4[3] += z4.w * wv;
    }
    float bb = b1[tid];
    int ks = tid >> 3, k8 = tid & 7;
#pragma unroll
    for (int i = 0; i < 4; i++) {
        int r = r0 + i;
        float v = fmaxf(acc4[i] + bb, 0.f);
        unsigned hb = f2tf32(v);
        unsigned lb = f2tf32(v - __uint_as_float(hb));
        int mt = r >> 4, r16 = r & 15;
        int lane = (r16 & 7) * 4 + (k8 & 3);
        int slot = ((r16 >> 3) & 1) | ((k8 >> 2) << 1);
        int idxF = ((ks * 64 + mt) * 2) * 128 + lane * 4 + slot;
        g_aF[idxF] = hb;
        g_aF[idxF + 128] = lb;
    }
}

// ----------------------------------------------------------------------------
// Host orchestration
// ----------------------------------------------------------------------------
extern "C" void kernel_launch(void* const* d_in, const int* in_sizes, int n_in,
                              void* d_out, int out_size)
{
    const float* hist   = (const float*)d_in[0];
    const float* coeffs = (const float*)d_in[1];
    const float* W_ih0 = (const float*)d_in[3];
    const float* W_hh0 = (const float*)d_in[4];
    const float* b_ih0 = (const float*)d_in[5];
    const float* b_hh0 = (const float*)d_in[6];
    const float* W_ih1 = (const float*)d_in[7];
    const float* W_hh1 = (const float*)d_in[8];
    const float* b_ih1 = (const float*)d_in[9];
    const float* b_hh1 = (const float*)d_in[10];
    const float* W_map = (const float*)d_in[11];
    const float* b_map = (const float*)d_in[12];
    const float* gamma = (const float*)d_in[13];
    const float* beta  = (const float*)d_in[14];
    const float* W1    = (const float*)d_in[15];
    const float* b1    = (const float*)d_in[16];
    const float* W2    = (const float*)d_in[17];
    const float* b2    = (const float*)d_in[18];
    const float* W_pred = (const float*)d_in[19];
    const float* b_pred = (const float*)d_in[20];
    float* out = (float*)d_out;

    float *p_xW, *p_seq0, *p_h1, *p_z, *p_f;
    cudaGetSymbolAddress((void**)&p_xW,   g_xW);
    cudaGetSymbolAddress((void**)&p_seq0, g_seq0);
    cudaGetSymbolAddress((void**)&p_h1,   g_h1);
    cudaGetSymbolAddress((void**)&p_z,    g_z);
    cudaGetSymbolAddress((void**)&p_f,    g_f);

    const int WSM_BYTES = 128 * 128 * 4;        // 64KB
    const int TC_SMEM   = 12288 * 4;            // 48KB (gemm_tf32)
    const int W2_SMEM   = 24576 * 4;            // 96KB (double-buffered)
    cudaFuncSetAttribute(lstm_persist, cudaFuncAttributeMaxDynamicSharedMemorySize, WSM_BYTES);
    cudaFuncSetAttribute(gemm_w2_tc, cudaFuncAttributeMaxDynamicSharedMemorySize, W2_SMEM);
    cudaFuncSetAttribute(gemm_tf32, cudaFuncAttributeMaxDynamicSharedMemorySize, TC_SMEM);

    zero_cnt<<<1, 64>>>();
    w2_frag<<<(W2_ROWS*128 + 255)/256, 256>>>(W2);

    // ---------------- LSTM layer 0 ----------------
    gemm_tf32<<<dim3(BB*T_HIST/128, G4/64), 256, TC_SMEM>>>(hist, W_ih0, nullptr, p_xW,
                                                            BB*T_HIST, G4, ENC_IN);
    lstm_persist<<<128, 256, WSM_BYTES>>>(p_xW, W_hh0, b_ih0, b_hh0,
                                          p_seq0, T_HIST*ENC_H, 0, T_HIST, 0);

    // ---------------- LSTM layer 1 ----------------
    gemm_tf32<<<dim3(BB*T_HIST/128, G4/64), 256, TC_SMEM>>>(p_seq0, W_ih1, nullptr, p_xW,
                                                            BB*T_HIST, G4, ENC_H);
    lstm_persist<<<128, 256, WSM_BYTES>>>(p_xW, W_hh1, b_ih1, b_hh1,
                                          p_h1, ENC_H, 1, T_HIST, 32);
    const float* context = p_h1 + (size_t)((T_HIST - 1) & 1) * BB * ENC_H;

    // ---------------- map to z0 ----------------
    gemm_tn<1><<<dim3(BB/64, 1), 256>>>(context, W_map, b_map, p_z, BB, CDE_H, ENC_H);

    // ---------------- Neural CDE, RK45 (Dormand-Prince) ----------------
    const double dt = 1.0 / N_STEPS;
    const double ACF[6][5] = {
        {0, 0, 0, 0, 0},
        {1.0/5, 0, 0, 0, 0},
        {3.0/40, 9.0/40, 0, 0, 0},
        {44.0/45, -56.0/15, 32.0/9, 0, 0},
        {19372.0/6561, -25360.0/2187, 64448.0/6561, -212.0/729, 0},
        {9017.0/3168, -355.0/33, 46732.0/5247, 49.0/176, -5103.0/18656}
    };
    const double COFF[6] = {0.0, 1.0/5, 3.0/10, 4.0/5, 8.0/9, 1.0};
    const double BU[5] = {35.0/384, 500.0/1113, 125.0/192, -2187.0/6784, 11.0/84};

    // initial prep for (i=0, s=0): no contract, nk=0
    cde_cp<<<256, 128>>>(coeffs, gamma, beta, W1, b1,
        0, 0, 0, 0.f, 0, 0.f, 0.f, 0.f, 0.f, 0.f,
        1, 0.f, 0.f, 0.f, 0.f, 0.f, 0);

    for (int it = 0; it < 96; it++) {
        int i = it / 6, s = it % 6;

        gemm_w2_tc<<<dim3(BB/128, W2_ROWS/64), 256, W2_SMEM>>>(b2, p_f);

        float ts = (float)((i + COFF[s]) * dt);
        int idx = (int)floorf(ts / 0.25f);
        if (idx < 0) idx = 0;
        if (idx > 3) idx = 3;
        float u = ts - (float)idx * 0.25f;

        int last = (s == 5);
        int do_prep = (it < 95);
        int nk = last ? 0 : (s + 1);
        const double* ar = last ? ACF[0] : ACF[s + 1];

        cde_cp<<<256, 128>>>(coeffs, gamma, beta, W1, b1,
            1, s, idx, u, last,
            (float)(dt*BU[0]), (float)(dt*BU[1]), (float)(dt*BU[2]),
            (float)(dt*BU[3]), (float)(dt*BU[4]),
            do_prep,
            (float)(dt*ar[0]), (float)(dt*ar[1]), (float)(dt*ar[2]),
            (float)(dt*ar[3]), (float)(dt*ar[4]), nk);
    }

    // ---------------- final projection ----------------
    gemm_tn<0><<<dim3(BB/64, (NZ + 63)/64), 256>>>(p_z, W_pred, b_pred, out,
                                                   BB, NZ, CDE_H);
}

// round 16
// speedup vs baseline: 1.1443x; 1.0245x over previous
#include <cuda_runtime.h>
#include <cuda_bf16.h>

#define BB 1024
#define T_HIST 50
#define ENC_IN 96
#define ENC_H 128
#define G4 (4*ENC_H)          // 512
#define CDE_H 64
#define CHN 33
#define NZ 10000
#define MLP_H 128
#define W2_ROWS (CHN*CDE_H)   // 2112
#define N_STEPS 16

// ----------------------------------------------------------------------------
// Scratch (static device globals — no allocation)
// ----------------------------------------------------------------------------
__device__ float g_xW[BB*T_HIST*G4];
__device__ float g_seq0[BB*T_HIST*ENC_H];
__device__ float g_h1[2][BB*ENC_H];
__device__ float g_z[BB*CDE_H];
__device__ float g_k[6][BB*CDE_H];
__device__ float g_f[BB*W2_ROWS];

// tf32 fragment-ordered operands for the W2 GEMM
__device__ unsigned g_aF[262144];
__device__ unsigned g_w2F[540672];

// per-batch-group LSTM sync counters (32 per layer)
__device__ unsigned g_grpCnt[64];

__global__ void zero_cnt() {
    if (threadIdx.x < 64) g_grpCnt[threadIdx.x] = 0u;
}

// ----------------------------------------------------------------------------
// tf32 / cp.async helpers (portable PTX — ptxas here targets plain sm_103)
// ----------------------------------------------------------------------------
__device__ __forceinline__ unsigned f2tf32(float v) {
    unsigned r;
    asm("cvt.rna.tf32.f32 %0, %1;" : "=r"(r) : "f"(v));
    return r;
}
__device__ __forceinline__ void mma_tf32(float c[4], uint4 a, uint2 b) {
    asm volatile(
        "mma.sync.aligned.m16n8k8.row.col.f32.tf32.tf32.f32 "
        "{%0,%1,%2,%3}, {%4,%5,%6,%7}, {%8,%9}, {%0,%1,%2,%3};"
        : "+f"(c[0]), "+f"(c[1]), "+f"(c[2]), "+f"(c[3])
        : "r"(a.x), "r"(a.y), "r"(a.z), "r"(a.w), "r"(b.x), "r"(b.y));
}
__device__ __forceinline__ unsigned smem_u32(const void* p) {
    unsigned a;
    asm("{ .reg .u64 t; cvta.to.shared.u64 t, %1; cvt.u32.u64 %0, t; }"
        : "=r"(a) : "l"(p));
    return a;
}
__device__ __forceinline__ void cp_async16(unsigned dst, const void* src) {
    asm volatile("cp.async.cg.shared.global [%0], [%1], 16;"
                 :: "r"(dst), "l"(src));
}
__device__ __forceinline__ void cp_commit() {
    asm volatile("cp.async.commit_group;" ::: "memory");
}
template<int N>
__device__ __forceinline__ void cp_wait() {
    asm volatile("cp.async.wait_group %0;" :: "n"(N) : "memory");
}

// ----------------------------------------------------------------------------
// One-time W2 -> tf32 hi/lo fragment-order conversion (per launch).
// ----------------------------------------------------------------------------
__global__ void __launch_bounds__(256)
w2_frag(const float* __restrict__ W2)
{
    int e = blockIdx.x * 256 + threadIdx.x;
    if (e >= W2_ROWS * 128) return;
    int n = e >> 7, k = e & 127;
    float v = W2[e];
    unsigned hb = f2tf32(v);
    unsigned lb = f2tf32(v - __uint_as_float(hb));
    int ks = k >> 3, k8 = k & 7, nt = n >> 3;
    int lane = (n & 7) * 4 + (k8 & 3);
    int slot = k8 >> 2;
    int idx = ((ks * 264 + nt) * 2) * 64 + lane * 2 + slot;
    g_w2F[idx] = hb;
    g_w2F[idx + 64] = lb;
}

// ----------------------------------------------------------------------------
// W2 GEMM via 3xTF32 mma.sync, pre-fragmented operands, cp.async double-
// buffered. NEW: 256x64 CTA tile (grid 4x33 = 132 CTAs, 1/SM, one even wave;
// halves B L2-traffic and per-CTA fixed overhead vs 128x64).
// 256 thr, 8 warps (4m x 2n), warp tile 64x32, K chunked by 32.
// Stage = A 64KB + B 16KB = 80KB; x2 = 160KB dynamic smem.
// ----------------------------------------------------------------------------
#define W2_STAGE_U32 20480

__device__ __forceinline__ void w2_load_chunk256(unsigned sbase, int c, int bx, int by,
                                                 int tid)
{
    const uint4* srcA = (const uint4*)g_aF;
    const uint4* srcB = (const uint4*)g_w2F;
    unsigned sA = sbase;                        // 16384 u32 region
    unsigned sB = sbase + 16384 * 4;            // 4096 u32 region
    // A: 4096 uint4 (16/thread). smem block (ksl*16+mtl)*2+hl, 32 uint4 each.
#pragma unroll
    for (int q = 0; q < 16; q++) {
        int e4 = tid + q * 256;
        int blk = e4 >> 5, w32 = e4 & 31;
        int ksl = blk >> 5, rest = blk & 31;    // mtl = rest>>1, hl = rest&1
        int gblk = (((c * 4 + ksl) * 64) + bx * 16 + (rest >> 1)) * 2 + (rest & 1);
        cp_async16(sA + e4 * 16, &srcA[gblk * 32 + w32]);
    }
    // B: 1024 uint4 (4/thread). smem block (ksl*8+ntl)*2+hl, 16 uint4 each.
#pragma unroll
    for (int q = 0; q < 4; q++) {
        int e4 = tid + q * 256;
        int blk = e4 >> 4, w16 = e4 & 15;
        int ksl = blk >> 4, rest = blk & 15;    // ntl = rest>>1, hl = rest&1
        int gblk = ((c * 4 + ksl) * 264 + by * 8 + (rest >> 1)) * 2 + (rest & 1);
        cp_async16(sB + e4 * 16, &srcB[gblk * 16 + w16]);
    }
    cp_commit();
}

__global__ void __launch_bounds__(256)
gemm_w2_tc(const float* __restrict__ b2, float* __restrict__ Fout)
{
    extern __shared__ __align__(16) unsigned pool[];   // 40960 u32 = 160KB
    const int tid = threadIdx.x;
    const int w = tid >> 5, l = tid & 31;
    const int wm = w & 3, wn = w >> 2;
    const int bx = blockIdx.x, by = blockIdx.y;
    const int m0 = bx * 256, n0 = by * 64;
    const unsigned sbase = smem_u32(pool);

    float acc[4][4][4];
#pragma unroll
    for (int mt = 0; mt < 4; mt++)
#pragma unroll
        for (int nt = 0; nt < 4; nt++)
#pragma unroll
            for (int i = 0; i < 4; i++) acc[mt][nt][i] = 0.f;

    w2_load_chunk256(sbase, 0, bx, by, tid);

    for (int c = 0; c < 4; c++) {
        if (c < 3) {
            w2_load_chunk256(sbase + ((c + 1) & 1) * W2_STAGE_U32 * 4, c + 1, bx, by, tid);
            cp_wait<1>();
        } else {
            cp_wait<0>();
        }
        __syncthreads();

        unsigned* As = pool + (c & 1) * W2_STAGE_U32;
        unsigned* Bs = As + 16384;
#pragma unroll
        for (int kstep = 0; kstep < 4; kstep++) {
            uint2 Bhi[4], Blo[4];
#pragma unroll
            for (int nt = 0; nt < 4; nt++) {
                int ntile = wn * 4 + nt;
                int base = ((kstep * 8 + ntile) * 2) * 64 + l * 2;
                Bhi[nt] = *(const uint2*)&Bs[base];
                Blo[nt] = *(const uint2*)&Bs[base + 64];
            }
#pragma unroll
            for (int mt = 0; mt < 4; mt++) {
                int mtile = wm * 4 + mt;
                int base = ((kstep * 16 + mtile) * 2) * 128 + l * 4;
                uint4 Ahi = *(const uint4*)&As[base];
                uint4 Alo = *(const uint4*)&As[base + 128];
#pragma unroll
                for (int nt = 0; nt < 4; nt++) {
                    mma_tf32(acc[mt][nt], Ahi, Bhi[nt]);
                    mma_tf32(acc[mt][nt], Ahi, Blo[nt]);
                    mma_tf32(acc[mt][nt], Alo, Bhi[nt]);
                }
            }
        }
        __syncthreads();
    }

    // epilogue: fragments -> padded smem (256x68) -> coalesced float4 stores
    float* S = (float*)pool;
    const int g = l >> 2, tq = l & 3;
#pragma unroll
    for (int mt = 0; mt < 4; mt++)
#pragma unroll
        for (int nt = 0; nt < 4; nt++) {
            int row = wm * 64 + mt * 16 + g;
            int col = wn * 32 + nt * 8 + tq * 2;
            S[row * 68 + col]           = acc[mt][nt][0];
            S[row * 68 + col + 1]       = acc[mt][nt][1];
            S[(row + 8) * 68 + col]     = acc[mt][nt][2];
            S[(row + 8) * 68 + col + 1] = acc[mt][nt][3];
        }
    __syncthreads();
#pragma unroll
    for (int q = 0; q < 16; q++) {
        int e = tid + q * 256;                  // 0..4095 float4 units
        int r = e >> 4, c4 = (e & 15) * 4;
        float4 v = *(const float4*)&S[r * 68 + c4];
        float4 o;
        o.x = tanhf(v.x + b2[n0 + c4 + 0]);
        o.y = tanhf(v.y + b2[n0 + c4 + 1]);
        o.z = tanhf(v.z + b2[n0 + c4 + 2]);
        o.w = tanhf(v.w + b2[n0 + c4 + 3]);
        *(float4*)&Fout[(size_t)(m0 + r) * W2_ROWS + n0 + c4] = o;
    }
}

// ----------------------------------------------------------------------------
// Generalized 3xTF32 GEMM: C = A @ B^T (+bias). (round-12 verified, unchanged)
// ----------------------------------------------------------------------------
__global__ void __launch_bounds__(256)
gemm_tf32(const float* __restrict__ A, const float* __restrict__ Bm,
          const float* __restrict__ bias, float* __restrict__ C,
          int M, int N, int K)
{
    extern __shared__ unsigned pool[];
    unsigned* As = pool;
    unsigned* Bs = pool + 8192;
    const int tid = threadIdx.x;
    const int w = tid >> 5, l = tid & 31;
    const int wm = w & 3, wn = w >> 2;
    const int m0 = blockIdx.x * 128, n0 = blockIdx.y * 64;
    const int KC = K >> 5;

    float acc[2][4][4];
#pragma unroll
    for (int mt = 0; mt < 2; mt++)
#pragma unroll
        for (int nt = 0; nt < 4; nt++)
#pragma unroll
            for (int i = 0; i < 4; i++) acc[mt][nt][i] = 0.f;

    for (int c = 0; c < KC; c++) {
        const int k0 = c * 32;
        if (c) __syncthreads();
#pragma unroll
        for (int q = 0; q < 16; q++) {
            int e = tid + q * 256;
            int r = e >> 5, kk = e & 31;
            float v = A[(size_t)(m0 + r) * K + k0 + kk];
            unsigned hb = f2tf32(v);
            unsigned lb = f2tf32(v - __uint_as_float(hb));
            int kstep = kk >> 3, k8 = kk & 7;
            int mtile = r >> 4, r16 = r & 15;
            int lane = (r16 & 7) * 4 + (k8 & 3);
            int slot = ((r16 >> 3) & 1) | ((k8 >> 2) << 1);
            int base = ((kstep * 8 + mtile) * 2) * 128 + lane * 4 + slot;
            As[base] = hb;
            As[base + 128] = lb;
        }
#pragma unroll
        for (int q = 0; q < 8; q++) {
            int e = tid + q * 256;
            int n = e >> 5, kk = e & 31;
            float v = Bm[(size_t)(n0 + n) * K + k0 + kk];
            unsigned hb = f2tf32(v);
            unsigned lb = f2tf32(v - __uint_as_float(hb));
            int kstep = kk >> 3, k8 = kk & 7;
            int ntile = n >> 3;
            int lane = (n & 7) * 4 + (k8 & 3);
            int slot = (k8 >> 2) & 1;
            int base = ((kstep * 8 + ntile) * 2) * 64 + lane * 2 + slot;
            Bs[base] = hb;
            Bs[base + 64] = lb;
        }
        __syncthreads();

#pragma unroll
        for (int kstep = 0; kstep < 4; kstep++) {
            uint4 Ahi[2], Alo[2];
            uint2 Bhi[4], Blo[4];
#pragma unroll
            for (int mt = 0; mt < 2; mt++) {
                int mtile = wm * 2 + mt;
                int base = ((kstep * 8 + mtile) * 2) * 128 + l * 4;
                Ahi[mt] = *(const uint4*)&As[base];
                Alo[mt] = *(const uint4*)&As[base + 128];
            }
#pragma unroll
            for (int nt = 0; nt < 4; nt++) {
                int ntile = wn * 4 + nt;
                int base = ((kstep * 8 + ntile) * 2) * 64 + l * 2;
                Bhi[nt] = *(const uint2*)&Bs[base];
                Blo[nt] = *(const uint2*)&Bs[base + 64];
            }
#pragma unroll
            for (int mt = 0; mt < 2; mt++)
#pragma unroll
                for (int nt = 0; nt < 4; nt++) {
                    mma_tf32(acc[mt][nt], Ahi[mt], Bhi[nt]);
                    mma_tf32(acc[mt][nt], Ahi[mt], Blo[nt]);
                    mma_tf32(acc[mt][nt], Alo[mt], Bhi[nt]);
                }
        }
    }

    __syncthreads();
    float* S = (float*)pool;
    const int g = l >> 2, tq = l & 3;
#pragma unroll
    for (int mt = 0; mt < 2; mt++)
#pragma unroll
        for (int nt = 0; nt < 4; nt++) {
            int row = wm * 32 + mt * 16 + g;
            int col = wn * 32 + nt * 8 + tq * 2;
            S[row * 68 + col]           = acc[mt][nt][0];
            S[row * 68 + col + 1]       = acc[mt][nt][1];
            S[(row + 8) * 68 + col]     = acc[mt][nt][2];
            S[(row + 8) * 68 + col + 1] = acc[mt][nt][3];
        }
    __syncthreads();
#pragma unroll
    for (int q = 0; q < 8; q++) {
        int e = tid + q * 256;
        int r = e >> 4, c4 = (e & 15) * 4;
        float4 v = *(const float4*)&S[r * 68 + c4];
        if (bias) {
            v.x += bias[n0 + c4 + 0];
            v.y += bias[n0 + c4 + 1];
            v.z += bias[n0 + c4 + 2];
            v.w += bias[n0 + c4 + 3];
        }
        *(float4*)&C[(size_t)(m0 + r) * N + n0 + c4] = v;
    }
}

// ----------------------------------------------------------------------------
// Generic C = act(A @ B^T + bias). Scalar FFMA (z0 map + final projection).
// ----------------------------------------------------------------------------
template<int ACT>
__global__ void __launch_bounds__(256)
gemm_tn(const float* __restrict__ A, const float* __restrict__ Bm,
        const float* __restrict__ bias, float* __restrict__ C,
        int M, int N, int K)
{
    __shared__ __align__(16) float As[16][64];
    __shared__ __align__(16) float Bs[16][64];
    const int m0 = blockIdx.x * 64;
    const int n0 = blockIdx.y * 64;
    const int tid = threadIdx.x;
    const int tr = tid >> 4;
    const int tc = tid & 15;

    float acc[4][4];
#pragma unroll
    for (int i = 0; i < 4; i++)
#pragma unroll
        for (int j = 0; j < 4; j++) acc[i][j] = 0.f;

    const int ml = tid >> 2;
    const int kq = (tid & 3) * 4;

    for (int k0 = 0; k0 < K; k0 += 16) {
        {
            float4 v = *(const float4*)(A + (size_t)(m0 + ml) * K + k0 + kq);
            As[kq+0][ml] = v.x; As[kq+1][ml] = v.y; As[kq+2][ml] = v.z; As[kq+3][ml] = v.w;
            float4 w = make_float4(0.f, 0.f, 0.f, 0.f);
            if (n0 + ml < N)
                w = *(const float4*)(Bm + (size_t)(n0 + ml) * K + k0 + kq);
            Bs[kq+0][ml] = w.x; Bs[kq+1][ml] = w.y; Bs[kq+2][ml] = w.z; Bs[kq+3][ml] = w.w;
        }
        __syncthreads();
#pragma unroll
        for (int kk = 0; kk < 16; kk++) {
            float4 a4 = *(const float4*)&As[kk][tr*4];
            float4 b4 = *(const float4*)&Bs[kk][tc*4];
            float av[4] = {a4.x, a4.y, a4.z, a4.w};
            float bv[4] = {b4.x, b4.y, b4.z, b4.w};
#pragma unroll
            for (int i = 0; i < 4; i++)
#pragma unroll
                for (int j = 0; j < 4; j++) acc[i][j] += av[i] * bv[j];
        }
        __syncthreads();
    }

#pragma unroll
    for (int j = 0; j < 4; j++) {
        int n = n0 + tc*4 + j;
        if (n >= N) continue;
        float bb = bias ? bias[n] : 0.f;
#pragma unroll
        for (int i = 0; i < 4; i++) {
            float v = acc[i][j] + bb;
            if (ACT == 1) v = tanhf(v);
            else if (ACT == 2) v = fmaxf(v, 0.f);
            C[(size_t)(m0 + tr*4 + i) * N + n] = v;
        }
    }
}

// ----------------------------------------------------------------------------
// Persistent LSTM layer — round-14 version (436us/layer), unchanged.
// ----------------------------------------------------------------------------
__global__ void __launch_bounds__(256)
lstm_persist(const float* __restrict__ xw,
             const float* __restrict__ Whh,
             const float* __restrict__ bih, const float* __restrict__ bhh,
             float* __restrict__ h_buf, int h_sb, int mode, int nsteps, int cbase)
{
    extern __shared__ __align__(16) float Wsm[];   // [128 k][128 c] = 64KB
    __shared__ __align__(16) float As[ENC_H][36];
    __shared__ __align__(16) float Gs[32][132];
    __shared__ float bsum[128];

    const int grp = blockIdx.x & 31;
    const int b0 = grp * 32;
    const int h0 = (blockIdx.x >> 5) * 32;
    const int tid = threadIdx.x;
    const int tr = tid >> 5;
    const int tc = tid & 31;

#pragma unroll
    for (int q = 0; q < 16; q++) {
        int e = tid + q * 256;
        int c = e & 127, kq = (e >> 7) * 4;
        int jg = (c >> 5) * ENC_H + h0 + (c & 31);
        float4 v = *(const float4*)(Whh + (size_t)jg * ENC_H + kq);
        Wsm[(kq+0)*128 + c] = v.x; Wsm[(kq+1)*128 + c] = v.y;
        Wsm[(kq+2)*128 + c] = v.z; Wsm[(kq+3)*128 + c] = v.w;
    }
    if (tid < 128) {
        int jg = (tid >> 5) * ENC_H + h0 + (tid & 31);
        bsum[tid] = bih[jg] + bhh[jg];
    }
    float creg[4] = {0.f, 0.f, 0.f, 0.f};
    __syncthreads();

    const int cb = tc * 4;
    const int jg0 = (cb >> 5) * ENC_H + h0 + (cb & 31);

    for (int t = 0; t < nsteps; t++) {
        float4 xr[4];
#pragma unroll
        for (int i = 0; i < 4; i++) {
            xr[i] = *(const float4*)(xw + (size_t)(b0 + tr*4 + i) * (T_HIST*G4)
                                     + (size_t)t * G4 + jg0);
        }

        float acc[4][4];
#pragma unroll
        for (int i = 0; i < 4; i++)
#pragma unroll
            for (int j = 0; j < 4; j++) acc[i][j] = 0.f;

        if (t > 0) {
            if (tid == 0) {
                while (__ldcg(&g_grpCnt[cbase + grp]) < 4u * (unsigned)t)
                    __nanosleep(20);
            }
            __syncthreads();
            const float* hp = h_buf + (mode ? (size_t)((t-1) & 1) * BB * ENC_H
                                            : (size_t)(t-1) * ENC_H);
#pragma unroll
            for (int q = 0; q < 4; q++) {
                int e = tid + q * 256;
                int m = e & 31, kq = (e >> 5) * 4;
                float4 v = __ldcg((const float4*)(hp + (size_t)(b0 + m) * h_sb + kq));
                As[kq+0][m] = v.x; As[kq+1][m] = v.y; As[kq+2][m] = v.z; As[kq+3][m] = v.w;
            }
            __syncthreads();
#pragma unroll 8
            for (int kk = 0; kk < ENC_H; kk++) {
                float4 a4 = *(const float4*)&As[kk][tr*4];
                float4 w4 = *(const float4*)&Wsm[kk*128 + cb];
                float av[4] = {a4.x, a4.y, a4.z, a4.w};
                float wv[4] = {w4.x, w4.y, w4.z, w4.w};
#pragma unroll
                for (int i = 0; i < 4; i++)
#pragma unroll
                    for (int j = 0; j < 4; j++) acc[i][j] += av[i] * wv[j];
            }
        }

#pragma unroll
        for (int i = 0; i < 4; i++) {
            float4 g;
            g.x = acc[i][0] + xr[i].x + bsum[cb + 0];
            g.y = acc[i][1] + xr[i].y + bsum[cb + 1];
            g.z = acc[i][2] + xr[i].z + bsum[cb + 2];
            g.w = acc[i][3] + xr[i].w + bsum[cb + 3];
            *(float4*)&Gs[tr*4 + i][cb] = g;
        }
        __syncthreads();

        float* ho = h_buf + (mode ? (size_t)(t & 1) * BB * ENC_H : (size_t)t * ENC_H);
#pragma unroll
        for (int q = 0; q < 4; q++) {
            int e = tid + q * 256;
            int r = e >> 5, hh = e & 31;
            float gi = Gs[r][hh];
            float gf = Gs[r][32 + hh];
            float gg = Gs[r][64 + hh];
            float go = Gs[r][96 + hh];
            float si = 1.f / (1.f + expf(-gi));
            float sf = 1.f / (1.f + expf(-gf));
            float so = 1.f / (1.f + expf(-go));
            float tg = tanhf(gg);
            float cn = sf * creg[q] + si * tg;
            creg[q] = cn;
            float hn = so * tanhf(cn);
            ho[(size_t)(b0 + r) * h_sb + h0 + hh] = hn;
        }
        __syncthreads();
        if (tid == 0) {
            __threadfence();
            atomicAdd(&g_grpCnt[cbase + grp], 1u);
        }
    }
}

// ----------------------------------------------------------------------------
// Fused CDE kernel: contract(stage sidx) + prep(next stage). (round-12
// verified) grid = 256 CTAs (4 batch rows each), 128 threads.
// ----------------------------------------------------------------------------
__global__ void __launch_bounds__(128)
cde_cp(const float* __restrict__ coeffs,
       const float* __restrict__ gamma, const float* __restrict__ beta,
       const float* __restrict__ W1, const float* __restrict__ b1,
       int do_contract, int sidx, int idx, float u, int is_last,
       float c1, float c3, float c4, float c5, float c6,
       int do_prep, float a0, float a1, float a2, float a3, float a4, int nk)
{
    __shared__ float W1s[64 * 128];              // 32KB, [k][j]
    __shared__ float zs[4][65];
    __shared__ float dXs[4][CHN];
    __shared__ __align__(16) float znT[64][4];
    const int r0 = blockIdx.x * 4;
    const int tid = threadIdx.x;

    if (do_prep) {
#pragma unroll
        for (int q = 0; q < 64; q++) {
            int e = tid + q * 128;
            int j = e >> 6, k = e & 63;
            W1s[k * 128 + j] = W1[e];
        }
    }

    if (do_contract) {
        for (int e = tid; e < 4 * CHN; e += 128) {
            int r = e / CHN, ch = e - r * CHN;
            size_t base = ((size_t)(r0 + r) * 4 + idx) * (4 * CHN);
            float A1 = coeffs[base + CHN + ch];
            float A2 = coeffs[base + 2 * CHN + ch];
            float A3 = coeffs[base + 3 * CHN + ch];
            dXs[r][ch] = A1 + 2.f * A2 * u + 3.f * A3 * u * u;
        }
        __syncthreads();
        const float av[5] = {a0, a1, a2, a3, a4};
#pragma unroll
        for (int q = 0; q < 2; q++) {
            int e = tid + q * 128;
            int r = e >> 6, h = e & 63;
            const float* fr = g_f + (size_t)(r0 + r) * W2_ROWS + h * CHN;
            float acc = 0.f;
#pragma unroll
            for (int ch = 0; ch < CHN; ch++) acc += fr[ch] * dXs[r][ch];
            size_t gi = (size_t)(r0 + r) * CDE_H + h;
            if (is_last) {
                float z = g_z[gi] + c1 * g_k[0][gi] + c3 * g_k[2][gi]
                        + c4 * g_k[3][gi] + c5 * g_k[4][gi] + c6 * acc;
                g_z[gi] = z;
                zs[r][h] = z;
            } else {
                g_k[sidx][gi] = acc;
                float v = g_z[gi];
                for (int j = 0; j < nk; j++)
                    v += av[j] * ((j == sidx) ? acc : g_k[j][gi]);
                zs[r][h] = v;
            }
        }
    } else {
#pragma unroll
        for (int q = 0; q < 2; q++) {
            int e = tid + q * 128;
            int r = e >> 6, h = e & 63;
            zs[r][h] = g_z[(size_t)(r0 + r) * CDE_H + h];
        }
    }
    if (!do_prep) return;
    __syncthreads();

    {
        int w = tid >> 5, lane = tid & 31;
        float x0 = zs[w][lane], x1 = zs[w][lane + 32];
        float s = x0 + x1;
#pragma unroll
        for (int d = 1; d < 32; d <<= 1) s += __shfl_xor_sync(0xffffffffu, s, d);
        float m = s * (1.f / 64.f);
        float d0 = x0 - m, d1 = x1 - m;
        float q2 = d0 * d0 + d1 * d1;
#pragma unroll
        for (int d = 1; d < 32; d <<= 1) q2 += __shfl_xor_sync(0xffffffffu, q2, d);
        float rs = rsqrtf(q2 * (1.f / 64.f) + 1e-5f);
        znT[lane][w]      = d0 * rs * gamma[lane] + beta[lane];
        znT[lane + 32][w] = d1 * rs * gamma[lane + 32] + beta[lane + 32];
    }
    __syncthreads();

    float acc4[4] = {0.f, 0.f, 0.f, 0.f};
#pragma unroll 8
    for (int k = 0; k < 64; k++) {
        float4 z4 = *(const float4*)&znT[k][0];
        float wv = W1s[k * 128 + tid];
        acc4[0] += z4.x * wv; acc4[1] += z4.y * wv;
        acc4[2] += z4.z * wv; acc4[3] += z4.w * wv;
    }
    float bb = b1[tid];
    int ks = tid >> 3, k8 = tid & 7;
#pragma unroll
    for (int i = 0; i < 4; i++) {
        int r = r0 + i;
        float v = fmaxf(acc4[i] + bb, 0.f);
        unsigned hb = f2tf32(v);
        unsigned lb = f2tf32(v - __uint_as_float(hb));
        int mt = r >> 4, r16 = r & 15;
        int lane = (r16 & 7) * 4 + (k8 & 3);
        int slot = ((r16 >> 3) & 1) | ((k8 >> 2) << 1);
        int idxF = ((ks * 64 + mt) * 2) * 128 + lane * 4 + slot;
        g_aF[idxF] = hb;
        g_aF[idxF + 128] = lb;
    }
}

// ----------------------------------------------------------------------------
// Host orchestration
// ----------------------------------------------------------------------------
extern "C" void kernel_launch(void* const* d_in, const int* in_sizes, int n_in,
                              void* d_out, int out_size)
{
    const float* hist   = (const float*)d_in[0];
    const float* coeffs = (const float*)d_in[1];
    const float* W_ih0 = (const float*)d_in[3];
    const float* W_hh0 = (const float*)d_in[4];
    const float* b_ih0 = (const float*)d_in[5];
    const float* b_hh0 = (const float*)d_in[6];
    const float* W_ih1 = (const float*)d_in[7];
    const float* W_hh1 = (const float*)d_in[8];
    const float* b_ih1 = (const float*)d_in[9];
    const float* b_hh1 = (const float*)d_in[10];
    const float* W_map = (const float*)d_in[11];
    const float* b_map = (const float*)d_in[12];
    const float* gamma = (const float*)d_in[13];
    const float* beta  = (const float*)d_in[14];
    const float* W1    = (const float*)d_in[15];
    const float* b1    = (const float*)d_in[16];
    const float* W2    = (const float*)d_in[17];
    const float* b2    = (const float*)d_in[18];
    const float* W_pred = (const float*)d_in[19];
    const float* b_pred = (const float*)d_in[20];
    float* out = (float*)d_out;

    float *p_xW, *p_seq0, *p_h1, *p_z, *p_f;
    cudaGetSymbolAddress((void**)&p_xW,   g_xW);
    cudaGetSymbolAddress((void**)&p_seq0, g_seq0);
    cudaGetSymbolAddress((void**)&p_h1,   g_h1);
    cudaGetSymbolAddress((void**)&p_z,    g_z);
    cudaGetSymbolAddress((void**)&p_f,    g_f);

    const int WSM_BYTES = 128 * 128 * 4;        // 64KB
    const int TC_SMEM   = 12288 * 4;            // 48KB (gemm_tf32)
    const int W2_SMEM   = 2 * W2_STAGE_U32 * 4; // 160KB (double-buffered 256x64)
    cudaFuncSetAttribute(lstm_persist, cudaFuncAttributeMaxDynamicSharedMemorySize, WSM_BYTES);
    cudaFuncSetAttribute(gemm_w2_tc, cudaFuncAttributeMaxDynamicSharedMemorySize, W2_SMEM);
    cudaFuncSetAttribute(gemm_tf32, cudaFuncAttributeMaxDynamicSharedMemorySize, TC_SMEM);

    zero_cnt<<<1, 64>>>();
    w2_frag<<<(W2_ROWS*128 + 255)/256, 256>>>(W2);

    // ---------------- LSTM layer 0 ----------------
    gemm_tf32<<<dim3(BB*T_HIST/128, G4/64), 256, TC_SMEM>>>(hist, W_ih0, nullptr, p_xW,
                                                            BB*T_HIST, G4, ENC_IN);
    lstm_persist<<<128, 256, WSM_BYTES>>>(p_xW, W_hh0, b_ih0, b_hh0,
                                          p_seq0, T_HIST*ENC_H, 0, T_HIST, 0);

    // ---------------- LSTM layer 1 ----------------
    gemm_tf32<<<dim3(BB*T_HIST/128, G4/64), 256, TC_SMEM>>>(p_seq0, W_ih1, nullptr, p_xW,
                                                            BB*T_HIST, G4, ENC_H);
    lstm_persist<<<128, 256, WSM_BYTES>>>(p_xW, W_hh1, b_ih1, b_hh1,
                                          p_h1, ENC_H, 1, T_HIST, 32);
    const float* context = p_h1 + (size_t)((T_HIST - 1) & 1) * BB * ENC_H;

    // ---------------- map to z0 ----------------
    gemm_tn<1><<<dim3(BB/64, 1), 256>>>(context, W_map, b_map, p_z, BB, CDE_H, ENC_H);

    // ---------------- Neural CDE, RK45 (Dormand-Prince) ----------------
    const double dt = 1.0 / N_STEPS;
    const double ACF[6][5] = {
        {0, 0, 0, 0, 0},
        {1.0/5, 0, 0, 0, 0},
        {3.0/40, 9.0/40, 0, 0, 0},
        {44.0/45, -56.0/15, 32.0/9, 0, 0},
        {19372.0/6561, -25360.0/2187, 64448.0/6561, -212.0/729, 0},
        {9017.0/3168, -355.0/33, 46732.0/5247, 49.0/176, -5103.0/18656}
    };
    const double COFF[6] = {0.0, 1.0/5, 3.0/10, 4.0/5, 8.0/9, 1.0};
    const double BU[5] = {35.0/384, 500.0/1113, 125.0/192, -2187.0/6784, 11.0/84};

    // initial prep for (i=0, s=0): no contract, nk=0
    cde_cp<<<256, 128>>>(coeffs, gamma, beta, W1, b1,
        0, 0, 0, 0.f, 0, 0.f, 0.f, 0.f, 0.f, 0.f,
        1, 0.f, 0.f, 0.f, 0.f, 0.f, 0);

    for (int it = 0; it < 96; it++) {
        int i = it / 6, s = it % 6;

        gemm_w2_tc<<<dim3(BB/256, W2_ROWS/64), 256, W2_SMEM>>>(b2, p_f);

        float ts = (float)((i + COFF[s]) * dt);
        int idx = (int)floorf(ts / 0.25f);
        if (idx < 0) idx = 0;
        if (idx > 3) idx = 3;
        float u = ts - (float)idx * 0.25f;

        int last = (s == 5);
        int do_prep = (it < 95);
        int nk = last ? 0 : (s + 1);
        const double* ar = last ? ACF[0] : ACF[s + 1];

        cde_cp<<<256, 128>>>(coeffs, gamma, beta, W1, b1,
            1, s, idx, u, last,
            (float)(dt*BU[0]), (float)(dt*BU[1]), (float)(dt*BU[2]),
            (float)(dt*BU[3]), (float)(dt*BU[4]),
            do_prep,
            (float)(dt*ar[0]), (float)(dt*ar[1]), (float)(dt*ar[2]),
            (float)(dt*ar[3]), (float)(dt*ar[4]), nk);
    }

    // ---------------- final projection ----------------
    gemm_tn<0><<<dim3(BB/64, (NZ + 63)/64), 256>>>(p_z, W_pred, b_pred, out,
                                                   BB, NZ, CDE_H);
}